// round 3
// baseline (speedup 1.0000x reference)
#include <cuda_runtime.h>
#include <math.h>

// ---------------- problem constants ----------------
#define H      1024
#define H4     4096
#define SRC    128          // source length S
#define V      32000
#define NSTEPS 51
#define EOS_ID 2

#define NBLK   148
#define NTHR   512
#define WPB    (NTHR / 32)           // warps per block = 16
#define TW     (NBLK * WPB)          // total warps = 2368

#define TT     32                    // tokens per smem tile in P0
#define DYN_SMEM (TT * H * 4)        // 128 KB

// ---------------- device scratch (static: no allocations allowed) ----------------
__device__ float g_xpre[SRC * H4];        // W_ih_e @ x_t + b_ih + b_hh, per token  (2 MB)
__device__ float g_hbuf[2][H];
__device__ float g_cbuf[2][H];
__device__ float g_hs[SRC * H];           // encoder hidden states (512 KB)
__device__ float g_M[H * SRC];            // W_tl[:, :H] @ hs_all^T  (512 KB)
__device__ float g_pre[H];                // b_tl + W_tl[:, H:] @ ht
__device__ float g_sc[SRC];               // attention scores
__device__ float g_htnew[H];
__device__ unsigned long long g_amax[2];  // ping-pong packed argmax
__device__ volatile int g_bar[NBLK];
__device__ float g_scratch[(size_t)NSTEPS * V + 64];  // fallback output space

// ---------------- helpers ----------------
__device__ __forceinline__ void gbar(int gen) {
    __threadfence();            // release: make this thread's writes GPU-visible
    __syncthreads();
    if (threadIdx.x == 0) g_bar[blockIdx.x] = gen;
    if (threadIdx.x < NBLK) {
        while (g_bar[threadIdx.x] < gen) { }
    }
    __syncthreads();
    __threadfence();            // acquire: CCTL.IVALL invalidates L1D -> see remote writes
}

__device__ __forceinline__ float wred(float v) {
#pragma unroll
    for (int o = 16; o > 0; o >>= 1) v += __shfl_xor_sync(0xffffffffu, v, o);
    return v;
}

// lane-partial dot of 1024 floats (rows are 16B aligned: offsets are multiples of H)
__device__ __forceinline__ float dp1024(const float* __restrict__ w,
                                        const float* __restrict__ x, int lane) {
    const float4* w4 = (const float4*)w;
    const float4* x4 = (const float4*)x;
    float s = 0.f;
#pragma unroll
    for (int k = 0; k < 8; ++k) {
        float4 a = w4[lane + 32 * k];
        float4 b = x4[lane + 32 * k];
        s = fmaf(a.x, b.x, fmaf(a.y, b.y, fmaf(a.z, b.z, fmaf(a.w, b.w, s))));
    }
    return s;
}

// streaming (evict-first) variant: keeps the 131MB W_lt stream out of L2's resident set
__device__ __forceinline__ float dp1024_cs(const float* __restrict__ w,
                                           const float* __restrict__ x, int lane) {
    const float4* w4 = (const float4*)w;
    const float4* x4 = (const float4*)x;
    float s = 0.f;
#pragma unroll
    for (int k = 0; k < 8; ++k) {
        float4 a = __ldcs(w4 + lane + 32 * k);
        float4 b = x4[lane + 32 * k];
        s = fmaf(a.x, b.x, fmaf(a.y, b.y, fmaf(a.z, b.z, fmaf(a.w, b.w, s))));
    }
    return s;
}

__device__ __forceinline__ unsigned long long packmax(float v, int r) {
    unsigned u = __float_as_uint(v);
    u = (u & 0x80000000u) ? ~u : (u | 0x80000000u);  // order-preserving float->uint
    return (((unsigned long long)u) << 32) | (unsigned)(0x7fffffff - r); // tie -> lowest r
}
__device__ __forceinline__ int unpackidx(unsigned long long k) {
    return 0x7fffffff - (int)(unsigned)(k & 0xffffffffu);
}

__device__ __forceinline__ float sigf(float x) { return 1.f / (1.f + expf(-x)); }

// ---------------- init kernel (reset per graph replay) ----------------
__global__ void init_k() {
    int i = threadIdx.x;
    if (i < NBLK) g_bar[i] = 0;
    if (i < 2) g_amax[i] = 0ull;
    for (int j = i; j < H; j += blockDim.x) {
        g_hbuf[0][j] = 0.f; g_cbuf[0][j] = 0.f;
        g_hbuf[1][j] = 0.f; g_cbuf[1][j] = 0.f;
    }
}

// ---------------- the persistent kernel ----------------
__global__ void __launch_bounds__(NTHR, 1)
seq2seq_kernel(const int* __restrict__ src_ids,
               const float* __restrict__ emb_in,
               const float* __restrict__ Wih_e, const float* __restrict__ Whh_e,
               const float* __restrict__ bih_e, const float* __restrict__ bhh_e,
               const float* __restrict__ W_li,  const float* __restrict__ b_li,
               const float* __restrict__ emb_t,
               const float* __restrict__ Wih_d, const float* __restrict__ Whh_d,
               const float* __restrict__ bih_d, const float* __restrict__ bhh_d,
               const float* __restrict__ W_lt,  const float* __restrict__ b_lt,
               const float* __restrict__ W_tl,  const float* __restrict__ b_tl,
               float* __restrict__ toks_out, float* __restrict__ logits_out) {
    const int lane = threadIdx.x & 31;
    const int w    = threadIdx.x >> 5;
    const int JID  = w * NBLK + blockIdx.x;   // striped job id -> spreads BW over all SMs

    extern __shared__ float4 s_emb4[];        // P0 only: TT tokens x 256 float4 (128 KB)
    __shared__ float s_attw[SRC];
    __shared__ unsigned long long s_best[WPB];

    int gen = 0;
    int pp  = 0;

    // ---------- P0: g_xpre[t][r] = dot(W_ih_e[r], emb[src[t]]) + biases ----------
    // Token-tiled in smem (TT=32), 2 weight rows register-resident per warp.
    // Weight stream read SRC/TT=4 times (67 MB L2); smem crossbar ~halved by row pairing.
    for (int tile = 0; tile < SRC / TT; ++tile) {
        for (int idx = threadIdx.x; idx < TT * 256; idx += NTHR) {
            int tt  = idx >> 8;            // token within tile
            int kk  = idx & 255;           // float4 index within row
            int tok = src_ids[tile * TT + tt];
            s_emb4[idx] = ((const float4*)(emb_in + (size_t)tok * H))[kk];
        }
        __syncthreads();
        for (int rp = JID; rp < H4 / 2; rp += TW) {
            int r = rp * 2;
            const float4* wa = (const float4*)(Wih_e + (size_t)r * H);
            const float4* wb = (const float4*)(Wih_e + (size_t)(r + 1) * H);
            float4 A[8], B[8];
#pragma unroll
            for (int k = 0; k < 8; ++k) { A[k] = wa[lane + 32 * k]; B[k] = wb[lane + 32 * k]; }
            float biasA = bih_e[r] + bhh_e[r];
            float biasB = bih_e[r + 1] + bhh_e[r + 1];
            for (int tt = 0; tt < TT; ++tt) {
                const float4* e4 = s_emb4 + tt * 256;
                float pa = 0.f, pb = 0.f;
#pragma unroll
                for (int k = 0; k < 8; ++k) {
                    float4 e = e4[lane + 32 * k];
                    pa = fmaf(A[k].x, e.x, fmaf(A[k].y, e.y, fmaf(A[k].z, e.z, fmaf(A[k].w, e.w, pa))));
                    pb = fmaf(B[k].x, e.x, fmaf(B[k].y, e.y, fmaf(B[k].z, e.z, fmaf(B[k].w, e.w, pb))));
                }
                pa = wred(pa);
                pb = wred(pb);
                if (lane == 0) {
                    int t = tile * TT + tt;
                    g_xpre[t * H4 + r]     = pa + biasA;
                    g_xpre[t * H4 + r + 1] = pb + biasB;
                }
            }
        }
        __syncthreads();
    }
    gbar(++gen);

    // ---------- P1: encoder recurrence (fused matvec+pointwise, 1 barrier/step) ----------
    for (int t = 0; t < SRC; ++t) {
        const float* h  = g_hbuf[pp];
        const float* c  = g_cbuf[pp];
        float* h2 = g_hbuf[pp ^ 1];
        float* c2 = g_cbuf[pp ^ 1];
        int j = JID;
        if (j < H) {
            float acc[4];
#pragma unroll
            for (int k = 0; k < 4; ++k) {
                float p = dp1024(Whh_e + (size_t)(k * H + j) * H, h, lane);
                acc[k] = wred(p);
            }
            if (lane == 0) {
                float gi = sigf (acc[0] + g_xpre[t * H4 + 0 * H + j]);
                float gf = sigf (acc[1] + g_xpre[t * H4 + 1 * H + j]);
                float gg = tanhf(acc[2] + g_xpre[t * H4 + 2 * H + j]);
                float go = sigf (acc[3] + g_xpre[t * H4 + 3 * H + j]);
                float cn = gf * c[j] + gi * gg;
                float hn = go * tanhf(cn);
                c2[j] = cn; h2[j] = hn;
                g_hs[t * H + j] = hn;
            }
        }
        gbar(++gen);
        pp ^= 1;
    }

    // ---------- P2: M = W_tl_left @ hs^T, and wid0 = argmax(W_li @ h_final + b_li) ----------
    {
        const float* hfin = g_hbuf[pp];
        for (int r = JID; r < H; r += TW) {
            const float4* w4 = (const float4*)(W_tl + (size_t)r * (2 * H));
            float4 wreg[8];
#pragma unroll
            for (int k = 0; k < 8; ++k) wreg[k] = w4[lane + 32 * k];
            for (int s = 0; s < SRC; ++s) {
                const float4* x4 = (const float4*)(g_hs + s * H);
                float p = 0.f;
#pragma unroll
                for (int k = 0; k < 8; ++k) {
                    float4 b = x4[lane + 32 * k];
                    p = fmaf(wreg[k].x, b.x, fmaf(wreg[k].y, b.y,
                        fmaf(wreg[k].z, b.z, fmaf(wreg[k].w, b.w, p))));
                }
                p = wred(p);
                if (lane == 0) g_M[r * SRC + s] = p;
            }
        }
        unsigned long long best = 0ull;
        for (int r = JID; r < V; r += TW) {
            float p = dp1024_cs(W_li + (size_t)r * H, hfin, lane);
            p = wred(p);
            if (lane == 0) {
                p += b_li[r];
                unsigned long long k = packmax(p, r);
                if (k > best) best = k;
            }
        }
        if (lane == 0) s_best[w] = best;
        __syncthreads();
        if (threadIdx.x == 0) {
            unsigned long long m = 0ull;
            for (int i = 0; i < WPB; ++i) if (s_best[i] > m) m = s_best[i];
            atomicMax(&g_amax[1], m);
        }
    }
    gbar(++gen);

    // ---------- P3: first decoder LSTM step (x = emb_t[wid0], state = encoder final) ----------
    int wid_cur = unpackidx(g_amax[1]);
    bool done = (wid_cur == EOS_ID);
    {
        const float* h  = g_hbuf[pp];
        const float* c  = g_cbuf[pp];
        float* h2 = g_hbuf[pp ^ 1];
        float* c2 = g_cbuf[pp ^ 1];
        const float* x = emb_t + (size_t)wid_cur * H;
        int j = JID;
        if (j < H) {
            float acc[4];
#pragma unroll
            for (int k = 0; k < 4; ++k) {
                size_t ro = (size_t)(k * H + j) * H;
                float p = dp1024(Wih_d + ro, x, lane) + dp1024(Whh_d + ro, h, lane);
                acc[k] = wred(p);
            }
            if (lane == 0) {
                float gi = sigf (acc[0] + bih_d[0 * H + j] + bhh_d[0 * H + j]);
                float gf = sigf (acc[1] + bih_d[1 * H + j] + bhh_d[1 * H + j]);
                float gg = tanhf(acc[2] + bih_d[2 * H + j] + bhh_d[2 * H + j]);
                float go = sigf (acc[3] + bih_d[3 * H + j] + bhh_d[3 * H + j]);
                float cn = gf * c[j] + gi * gg;
                float hn = go * tanhf(cn);
                c2[j] = cn; h2[j] = hn;
            }
        }
    }
    gbar(++gen);
    pp ^= 1;

    // ---------- decode loop: 3 barriers per step ----------
    for (int t = 0; t < NSTEPS; ++t) {
        // ----- phase A: scores | fused LSTM (uses incoming wid) | W_tl_right @ ht -----
        if (t > 0) {
            unsigned long long key = g_amax[(t - 1) & 1];
            int wn = unpackidx(key);
            if (blockIdx.x == 0 && threadIdx.x == 0) {
                int ot = (done || wn == EOS_ID) ? -1 : wn;
                toks_out[t - 1] = (float)ot;
            }
            if (wn == EOS_ID) done = true;
            wid_cur = wn;
        }
        {
            const float* h  = g_hbuf[pp];
            const float* c  = g_cbuf[pp];
            float* h2 = g_hbuf[pp ^ 1];
            float* c2 = g_cbuf[pp ^ 1];
            if (JID < SRC) {
                int s = JID;
                float p = dp1024(g_hs + s * H, h, lane);
                p = wred(p);
                if (lane == 0) g_sc[s] = p;
            } else if (JID < SRC + H) {
                int j = JID - SRC;
                const float* x = emb_t + (size_t)wid_cur * H;
                float acc[4];
#pragma unroll
                for (int k = 0; k < 4; ++k) {
                    size_t ro = (size_t)(k * H + j) * H;
                    float p = dp1024(Wih_d + ro, x, lane) + dp1024(Whh_d + ro, h, lane);
                    acc[k] = wred(p);
                }
                if (lane == 0) {
                    float gi = sigf (acc[0] + bih_d[0 * H + j] + bhh_d[0 * H + j]);
                    float gf = sigf (acc[1] + bih_d[1 * H + j] + bhh_d[1 * H + j]);
                    float gg = tanhf(acc[2] + bih_d[2 * H + j] + bhh_d[2 * H + j]);
                    float go = sigf (acc[3] + bih_d[3 * H + j] + bhh_d[3 * H + j]);
                    float cn = gf * c[j] + gi * gg;
                    float hn = go * tanhf(cn);
                    c2[j] = cn; h2[j] = hn;
                }
            } else if (JID < SRC + H + H) {
                int r = JID - SRC - H;
                float p = dp1024(W_tl + (size_t)r * (2 * H) + H, h, lane);
                p = wred(p);
                if (lane == 0) g_pre[r] = p + b_tl[r];
            }
        }
        gbar(++gen);
        pp ^= 1;

        // ----- phase B: softmax (redundant per block) + ht_new = tanh(pre + M @ attw) -----
        if (w == 0) {
            float v0 = g_sc[lane], v1 = g_sc[lane + 32], v2 = g_sc[lane + 64], v3 = g_sc[lane + 96];
            float m = fmaxf(fmaxf(v0, v1), fmaxf(v2, v3));
#pragma unroll
            for (int o = 16; o > 0; o >>= 1) m = fmaxf(m, __shfl_xor_sync(0xffffffffu, m, o));
            float e0 = expf(v0 - m), e1 = expf(v1 - m), e2 = expf(v2 - m), e3 = expf(v3 - m);
            float ssum = wred(e0 + e1 + e2 + e3);
            float inv = 1.f / ssum;
            s_attw[lane]      = e0 * inv;
            s_attw[lane + 32] = e1 * inv;
            s_attw[lane + 64] = e2 * inv;
            s_attw[lane + 96] = e3 * inv;
        }
        if (blockIdx.x == 0 && threadIdx.x == 0) g_amax[(t + 1) & 1] = 0ull;  // safe: read >=2 barriers ago
        __syncthreads();
        if (JID < H) {
            int r = JID;
            float p = 0.f;
#pragma unroll
            for (int k = 0; k < 4; ++k)
                p += g_M[r * SRC + lane + 32 * k] * s_attw[lane + 32 * k];
            p = wred(p);
            if (lane == 0) g_htnew[r] = tanhf(g_pre[r] + p);
        }
        gbar(++gen);

        // ----- phase C: logits = W_lt @ ht_new + b_lt (streamed), argmax -----
        {
            unsigned long long best = 0ull;
            for (int r = JID; r < V; r += TW) {
                float p = dp1024_cs(W_lt + (size_t)r * H, g_htnew, lane);
                p = wred(p);
                if (lane == 0) {
                    p += b_lt[r];
                    __stcs(logits_out + (size_t)t * V + r, p);
                    unsigned long long k = packmax(p, r);
                    if (k > best) best = k;
                }
            }
            if (lane == 0) s_best[w] = best;
            __syncthreads();
            if (threadIdx.x == 0) {
                unsigned long long m = 0ull;
                for (int i = 0; i < WPB; ++i) if (s_best[i] > m) m = s_best[i];
                atomicMax(&g_amax[t & 1], m);
            }
        }
        gbar(++gen);
    }

    // ---------- epilogue: last token ----------
    if (blockIdx.x == 0 && threadIdx.x == 0) {
        int wn = unpackidx(g_amax[(NSTEPS - 1) & 1]);
        int ot = (done || wn == EOS_ID) ? -1 : wn;
        toks_out[NSTEPS - 1] = (float)ot;
    }
}

// ---------------- host launcher ----------------
extern "C" void kernel_launch(void* const* d_in, const int* in_sizes, int n_in,
                              void* d_out, int out_size) {
    const int*   src_ids = (const int*)  d_in[0];
    const float* emb_in  = (const float*)d_in[1];
    const float* Wih_e   = (const float*)d_in[2];
    const float* Whh_e   = (const float*)d_in[3];
    const float* bih_e   = (const float*)d_in[4];
    const float* bhh_e   = (const float*)d_in[5];
    const float* W_li    = (const float*)d_in[6];
    const float* b_li    = (const float*)d_in[7];
    const float* emb_t   = (const float*)d_in[8];
    const float* Wih_d   = (const float*)d_in[9];
    const float* Whh_d   = (const float*)d_in[10];
    const float* bih_d   = (const float*)d_in[11];
    const float* bhh_d   = (const float*)d_in[12];
    const float* W_lt    = (const float*)d_in[13];
    const float* b_lt    = (const float*)d_in[14];
    const float* W_tl    = (const float*)d_in[15];
    const float* b_tl    = (const float*)d_in[16];

    float* out = (float*)d_out;
    float* scratch = nullptr;
    cudaGetSymbolAddress((void**)&scratch, g_scratch);

    float* toks_out   = scratch + (size_t)NSTEPS * V;  // defaults into scratch
    float* logits_out = scratch;
    if (out_size >= NSTEPS * V + NSTEPS) {        // (toks, logits) concatenated
        toks_out   = out;
        logits_out = out + NSTEPS;
    } else if (out_size >= NSTEPS * V) {          // logits only
        logits_out = out;
    } else if (out_size >= NSTEPS) {              // toks only
        toks_out = out;
    }

    static int smem_set = 0;
    if (!smem_set) {
        cudaFuncSetAttribute(seq2seq_kernel,
                             cudaFuncAttributeMaxDynamicSharedMemorySize, DYN_SMEM);
        smem_set = 1;
    }

    init_k<<<1, 256>>>();
    seq2seq_kernel<<<NBLK, NTHR, DYN_SMEM>>>(src_ids, emb_in, Wih_e, Whh_e, bih_e, bhh_e,
                                             W_li, b_li, emb_t, Wih_d, Whh_d, bih_d, bhh_d,
                                             W_lt, b_lt, W_tl, b_tl, toks_out, logits_out);
}

// round 10
// speedup vs baseline: 1.4240x; 1.4240x over previous
#include <cuda_runtime.h>
#include <cuda_bf16.h>
#include <math.h>

// ---------------- problem constants ----------------
#define H      1024
#define H4     4096
#define SRC    128          // source length S
#define V      32000
#define NSTEPS 51
#define EOS_ID 2

#define NBLK   148
#define NTHR   512
#define WPB    (NTHR / 32)           // warps per block = 16
#define TW     (NBLK * WPB)          // total warps = 2368

#define TT     32                    // tokens per smem tile in P0
// dynamic smem: max(P0 emb tile 128KB, deferred htall 51*4KB = 204KB)
#define DYN_SMEM (NSTEPS * H * 4)    // 208896 B

// ---------------- device scratch (static: no allocations allowed) ----------------
__device__ float g_xpre[SRC * H4];        // W_ih_e @ x_t + biases, per token  (2 MB)
__device__ float g_hbuf[2][H];
__device__ float g_cbuf[2][H];
__device__ float g_hs[SRC * H];           // encoder hidden states (512 KB)
__device__ float g_M[H * SRC];            // W_tl[:, :H] @ hs_all^T  (512 KB)
__device__ float g_pre[H];                // b_tl + W_tl[:, H:] @ ht
__device__ float g_sc[SRC];               // attention scores
__device__ float g_htall[NSTEPS * H];     // all decoder ht_new vectors (204 KB)
__device__ unsigned int  g_wbf[(size_t)V * (H / 2)];   // bf16-packed W_lt (65.5 MB, L2-resident)
__device__ float g_bfsc[V];               // per-step bf16 scores (128 KB)
__device__ unsigned int g_wmax_bits;      // max row ||W_r||^2 (as uint bits, fp>=0)
__device__ float g_hnorm2;                // ||ht_new||^2 for current step
__device__ unsigned long long g_bfmax;    // packed bf16 max (per step)
__device__ unsigned long long g_amax[2];  // ping-pong packed fp32 argmax
__device__ unsigned int g_count;          // barrier arrival counter (monotonic)
__device__ volatile unsigned int g_flag;  // barrier generation flag (single line)
__device__ float g_scratch[(size_t)NSTEPS * V + 64];  // fallback output space

// ---------------- helpers ----------------
// Grid barrier: counter + flag, ONE poller per block on ONE cache line.
__device__ __forceinline__ void gbar(int gen) {
    __syncthreads();
    if (threadIdx.x == 0) {
        __threadfence();                              // release
        unsigned int t = atomicAdd(&g_count, 1u);
        if (t == (unsigned)(NBLK * gen - 1)) {
            g_flag = (unsigned)gen;
        } else {
            while (g_flag < (unsigned)gen) { }
        }
    }
    __syncthreads();
    __threadfence();            // acquire: CCTL.IVALL invalidates L1D
}

__device__ __forceinline__ float wred(float v) {
#pragma unroll
    for (int o = 16; o > 0; o >>= 1) v += __shfl_xor_sync(0xffffffffu, v, o);
    return v;
}

// lane-partial dot of 1024 floats; FMA order is LOAD-BEARING (must match deferred pass)
__device__ __forceinline__ float dp1024(const float* __restrict__ w,
                                        const float* __restrict__ x, int lane) {
    const float4* w4 = (const float4*)w;
    const float4* x4 = (const float4*)x;
    float s = 0.f;
#pragma unroll
    for (int k = 0; k < 8; ++k) {
        float4 a = w4[lane + 32 * k];
        float4 b = x4[lane + 32 * k];
        s = fmaf(a.x, b.x, fmaf(a.y, b.y, fmaf(a.z, b.z, fmaf(a.w, b.w, s))));
    }
    return s;
}

__device__ __forceinline__ float dp1024_cs(const float* __restrict__ w,
                                           const float* __restrict__ x, int lane) {
    const float4* w4 = (const float4*)w;
    const float4* x4 = (const float4*)x;
    float s = 0.f;
#pragma unroll
    for (int k = 0; k < 8; ++k) {
        float4 a = __ldcs(w4 + lane + 32 * k);
        float4 b = x4[lane + 32 * k];
        s = fmaf(a.x, b.x, fmaf(a.y, b.y, fmaf(a.z, b.z, fmaf(a.w, b.w, s))));
    }
    return s;
}

__device__ __forceinline__ unsigned long long packmax(float v, int r) {
    unsigned u = __float_as_uint(v);
    u = (u & 0x80000000u) ? ~u : (u | 0x80000000u);  // order-preserving float->uint
    return (((unsigned long long)u) << 32) | (unsigned)(0x7fffffff - r); // tie -> lowest r
}
__device__ __forceinline__ int unpackidx(unsigned long long k) {
    return 0x7fffffff - (int)(unsigned)(k & 0xffffffffu);
}
__device__ __forceinline__ float unpackval(unsigned long long k) {
    unsigned u = (unsigned)(k >> 32);
    u = (u & 0x80000000u) ? (u & 0x7fffffffu) : ~u;
    return __uint_as_float(u);
}

__device__ __forceinline__ float sigf(float x) { return 1.f / (1.f + expf(-x)); }

__device__ __forceinline__ unsigned int packbf2(float a, float b) {
    __nv_bfloat162 t = __floats2bfloat162_rn(a, b);   // .x = a, .y = b
    return *reinterpret_cast<unsigned int*>(&t);
}

// ---------------- init kernel (reset per graph replay) ----------------
__global__ void init_k() {
    int i = threadIdx.x;
    if (i == 0) { g_count = 0u; g_flag = 0u; g_wmax_bits = 0u; g_hnorm2 = 0.f; g_bfmax = 0ull; }
    if (i < 2) g_amax[i] = 0ull;
    for (int j = i; j < H; j += blockDim.x) {
        g_hbuf[0][j] = 0.f; g_cbuf[0][j] = 0.f;
        g_hbuf[1][j] = 0.f; g_cbuf[1][j] = 0.f;
    }
}

// ---------------- the persistent kernel ----------------
__global__ void __launch_bounds__(NTHR, 1)
seq2seq_kernel(const int* __restrict__ src_ids,
               const float* __restrict__ emb_in,
               const float* __restrict__ Wih_e, const float* __restrict__ Whh_e,
               const float* __restrict__ bih_e, const float* __restrict__ bhh_e,
               const float* __restrict__ W_li,  const float* __restrict__ b_li,
               const float* __restrict__ emb_t,
               const float* __restrict__ Wih_d, const float* __restrict__ Whh_d,
               const float* __restrict__ bih_d, const float* __restrict__ bhh_d,
               const float* __restrict__ W_lt,  const float* __restrict__ b_lt,
               const float* __restrict__ W_tl,  const float* __restrict__ b_tl,
               float* __restrict__ toks_out, float* __restrict__ logits_out) {
    const int lane = threadIdx.x & 31;
    const int w    = threadIdx.x >> 5;
    const int JID  = w * NBLK + blockIdx.x;

    extern __shared__ float4 s_dyn4[];        // P0: emb tiles; deferred: all ht_new
    __shared__ float s_attw[SRC];
    __shared__ unsigned long long s_best[WPB];

    int gen = 0;
    int pp  = 0;

    // ---------- P0a: g_xpre[t][r] = dot(W_ih_e[r], emb[src[t]]) + biases ----------
    for (int tile = 0; tile < SRC / TT; ++tile) {
        for (int idx = threadIdx.x; idx < TT * 256; idx += NTHR) {
            int tt  = idx >> 8;
            int kk  = idx & 255;
            int tok = src_ids[tile * TT + tt];
            s_dyn4[idx] = ((const float4*)(emb_in + (size_t)tok * H))[kk];
        }
        __syncthreads();
        for (int rp = JID; rp < H4 / 2; rp += TW) {
            int r = rp * 2;
            const float4* wa = (const float4*)(Wih_e + (size_t)r * H);
            const float4* wb = (const float4*)(Wih_e + (size_t)(r + 1) * H);
            float4 A[8], B[8];
#pragma unroll
            for (int k = 0; k < 8; ++k) { A[k] = wa[lane + 32 * k]; B[k] = wb[lane + 32 * k]; }
            float biasA = bih_e[r] + bhh_e[r];
            float biasB = bih_e[r + 1] + bhh_e[r + 1];
            for (int tt = 0; tt < TT; ++tt) {
                const float4* e4 = s_dyn4 + tt * 256;
                float pa = 0.f, pb = 0.f;
#pragma unroll
                for (int k = 0; k < 8; ++k) {
                    float4 e = e4[lane + 32 * k];
                    pa = fmaf(A[k].x, e.x, fmaf(A[k].y, e.y, fmaf(A[k].z, e.z, fmaf(A[k].w, e.w, pa))));
                    pb = fmaf(B[k].x, e.x, fmaf(B[k].y, e.y, fmaf(B[k].z, e.z, fmaf(B[k].w, e.w, pb))));
                }
                pa = wred(pa);
                pb = wred(pb);
                if (lane == 0) {
                    int t = tile * TT + tt;
                    g_xpre[t * H4 + r]     = pa + biasA;
                    g_xpre[t * H4 + r + 1] = pb + biasB;
                }
            }
        }
        __syncthreads();
    }

    // ---------- P0b: pack W_lt -> bf16 copy + max row-norm^2 ----------
    for (int r = JID; r < V; r += TW) {
        const float4* w4 = (const float4*)(W_lt + (size_t)r * H);
        uint4* ob = (uint4*)(g_wbf + (size_t)r * 512);
        float n2 = 0.f;
#pragma unroll
        for (int m = 0; m < 4; ++m) {
            float4 a = __ldcs(w4 + 2 * (lane + 32 * m));
            float4 b = __ldcs(w4 + 2 * (lane + 32 * m) + 1);
            n2 += a.x*a.x + a.y*a.y + a.z*a.z + a.w*a.w
                + b.x*b.x + b.y*b.y + b.z*b.z + b.w*b.w;
            uint4 o;
            o.x = packbf2(a.x, a.y);
            o.y = packbf2(a.z, a.w);
            o.z = packbf2(b.x, b.y);
            o.w = packbf2(b.z, b.w);
            ob[lane + 32 * m] = o;
        }
        n2 = wred(n2);
        if (lane == 0) atomicMax(&g_wmax_bits, __float_as_uint(n2));  // fp>=0: uint order ok
    }
    gbar(++gen);

    // ---------- P1: encoder recurrence ----------
    for (int t = 0; t < SRC; ++t) {
        const float* h  = g_hbuf[pp];
        const float* c  = g_cbuf[pp];
        float* h2 = g_hbuf[pp ^ 1];
        float* c2 = g_cbuf[pp ^ 1];
        int j = JID;
        if (j < H) {
            float acc[4];
#pragma unroll
            for (int k = 0; k < 4; ++k) {
                float p = dp1024(Whh_e + (size_t)(k * H + j) * H, h, lane);
                acc[k] = wred(p);
            }
            if (lane == 0) {
                float gi = sigf (acc[0] + g_xpre[t * H4 + 0 * H + j]);
                float gf = sigf (acc[1] + g_xpre[t * H4 + 1 * H + j]);
                float gg = tanhf(acc[2] + g_xpre[t * H4 + 2 * H + j]);
                float go = sigf (acc[3] + g_xpre[t * H4 + 3 * H + j]);
                float cn = gf * c[j] + gi * gg;
                float hn = go * tanhf(cn);
                c2[j] = cn; h2[j] = hn;
                g_hs[t * H + j] = hn;
            }
        }
        gbar(++gen);
        pp ^= 1;
    }

    // ---------- P2: M = W_tl_left @ hs^T, wid0 = argmax(W_li @ h_final + b_li) ----------
    {
        const float* hfin = g_hbuf[pp];
        for (int r = JID; r < H; r += TW) {
            const float4* w4 = (const float4*)(W_tl + (size_t)r * (2 * H));
            float4 wreg[8];
#pragma unroll
            for (int k = 0; k < 8; ++k) wreg[k] = w4[lane + 32 * k];
            for (int s = 0; s < SRC; ++s) {
                const float4* x4 = (const float4*)(g_hs + s * H);
                float p = 0.f;
#pragma unroll
                for (int k = 0; k < 8; ++k) {
                    float4 b = x4[lane + 32 * k];
                    p = fmaf(wreg[k].x, b.x, fmaf(wreg[k].y, b.y,
                        fmaf(wreg[k].z, b.z, fmaf(wreg[k].w, b.w, p))));
                }
                p = wred(p);
                if (lane == 0) g_M[r * SRC + s] = p;
            }
        }
        unsigned long long best = 0ull;
        for (int r = JID; r < V; r += TW) {
            float p = dp1024_cs(W_li + (size_t)r * H, hfin, lane);
            p = wred(p);
            if (lane == 0) {
                p += b_li[r];
                unsigned long long k = packmax(p, r);
                if (k > best) best = k;
            }
        }
        if (lane == 0) s_best[w] = best;
        __syncthreads();
        if (threadIdx.x == 0) {
            unsigned long long m = 0ull;
            for (int i = 0; i < WPB; ++i) if (s_best[i] > m) m = s_best[i];
            atomicMax(&g_amax[1], m);
        }
    }
    gbar(++gen);

    // ---------- P3: first decoder LSTM step ----------
    int wid_cur = unpackidx(g_amax[1]);
    bool done = (wid_cur == EOS_ID);
    {
        const float* h  = g_hbuf[pp];
        const float* c  = g_cbuf[pp];
        float* h2 = g_hbuf[pp ^ 1];
        float* c2 = g_cbuf[pp ^ 1];
        const float* x = emb_t + (size_t)wid_cur * H;
        int j = JID;
        if (j < H) {
            float acc[4];
#pragma unroll
            for (int k = 0; k < 4; ++k) {
                size_t ro = (size_t)(k * H + j) * H;
                float p = dp1024(Wih_d + ro, x, lane) + dp1024(Whh_d + ro, h, lane);
                acc[k] = wred(p);
            }
            if (lane == 0) {
                float gi = sigf (acc[0] + bih_d[0 * H + j] + bhh_d[0 * H + j]);
                float gf = sigf (acc[1] + bih_d[1 * H + j] + bhh_d[1 * H + j]);
                float gg = tanhf(acc[2] + bih_d[2 * H + j] + bhh_d[2 * H + j]);
                float go = sigf (acc[3] + bih_d[3 * H + j] + bhh_d[3 * H + j]);
                float cn = gf * c[j] + gi * gg;
                float hn = go * tanhf(cn);
                c2[j] = cn; h2[j] = hn;
            }
        }
    }
    gbar(++gen);
    pp ^= 1;

    // ---------- decode loop: 4 barriers per step ----------
    for (int t = 0; t < NSTEPS; ++t) {
        // ----- phase A: scores | fused LSTM | W_tl_right @ ht; zero step scalars -----
        if (t > 0) {
            unsigned long long key = g_amax[(t - 1) & 1];
            int wn = unpackidx(key);
            if (blockIdx.x == 0 && threadIdx.x == 0) {
                int ot = (done || wn == EOS_ID) ? -1 : wn;
                toks_out[t - 1] = (float)ot;
            }
            if (wn == EOS_ID) done = true;
            wid_cur = wn;
        }
        if (blockIdx.x == 0 && threadIdx.x == 0) {
            g_hnorm2 = 0.f;            // last read in C2 of prev step, strictly before A's barrier
            g_bfmax  = 0ull;           // ditto
        }
        {
            const float* h  = g_hbuf[pp];
            const float* c  = g_cbuf[pp];
            float* h2 = g_hbuf[pp ^ 1];
            float* c2 = g_cbuf[pp ^ 1];
            if (JID < SRC) {
                int s = JID;
                float p = dp1024(g_hs + s * H, h, lane);
                p = wred(p);
                if (lane == 0) g_sc[s] = p;
            } else if (JID < SRC + H) {
                int j = JID - SRC;
                const float* x = emb_t + (size_t)wid_cur * H;
                float acc[4];
#pragma unroll
                for (int k = 0; k < 4; ++k) {
                    size_t ro = (size_t)(k * H + j) * H;
                    float p = dp1024(Wih_d + ro, x, lane) + dp1024(Whh_d + ro, h, lane);
                    acc[k] = wred(p);
                }
                if (lane == 0) {
                    float gi = sigf (acc[0] + bih_d[0 * H + j] + bhh_d[0 * H + j]);
                    float gf = sigf (acc[1] + bih_d[1 * H + j] + bhh_d[1 * H + j]);
                    float gg = tanhf(acc[2] + bih_d[2 * H + j] + bhh_d[2 * H + j]);
                    float go = sigf (acc[3] + bih_d[3 * H + j] + bhh_d[3 * H + j]);
                    float cn = gf * c[j] + gi * gg;
                    float hn = go * tanhf(cn);
                    c2[j] = cn; h2[j] = hn;
                }
            } else if (JID < SRC + H + H) {
                int r = JID - SRC - H;
                float p = dp1024(W_tl + (size_t)r * (2 * H) + H, h, lane);
                p = wred(p);
                if (lane == 0) g_pre[r] = p + b_tl[r];
            }
        }
        gbar(++gen);
        pp ^= 1;

        // ----- phase B: softmax + ht_new = tanh(pre + M @ attw); accumulate ||ht_new||^2 -----
        if (w == 0) {
            float v0 = g_sc[lane], v1 = g_sc[lane + 32], v2 = g_sc[lane + 64], v3 = g_sc[lane + 96];
            float m = fmaxf(fmaxf(v0, v1), fmaxf(v2, v3));
#pragma unroll
            for (int o = 16; o > 0; o >>= 1) m = fmaxf(m, __shfl_xor_sync(0xffffffffu, m, o));
            float e0 = expf(v0 - m), e1 = expf(v1 - m), e2 = expf(v2 - m), e3 = expf(v3 - m);
            float ssum = wred(e0 + e1 + e2 + e3);
            float inv = 1.f / ssum;
            s_attw[lane]      = e0 * inv;
            s_attw[lane + 32] = e1 * inv;
            s_attw[lane + 64] = e2 * inv;
            s_attw[lane + 96] = e3 * inv;
        }
        if (blockIdx.x == 0 && threadIdx.x == 0) g_amax[(t + 1) & 1] = 0ull;
        __syncthreads();
        if (JID < H) {
            int r = JID;
            float p = 0.f;
#pragma unroll
            for (int k = 0; k < 4; ++k)
                p += g_M[r * SRC + lane + 32 * k] * s_attw[lane + 32 * k];
            p = wred(p);
            if (lane == 0) {
                float hn = tanhf(g_pre[r] + p);
                g_htall[t * H + r] = hn;
                atomicAdd(&g_hnorm2, hn * hn);
            }
        }
        gbar(++gen);

        // ----- phase C1: bf16 scores from L2-resident copy + global bf16 max -----
        {
            const float4* x4 = (const float4*)(g_htall + t * H);
            unsigned long long best = 0ull;
            for (int r = JID; r < V; r += TW) {
                const uint4* wb = (const uint4*)(g_wbf + (size_t)r * 512);
                float s = 0.f;
#pragma unroll
                for (int m = 0; m < 4; ++m) {
                    uint4 u = wb[lane + 32 * m];
                    float4 xa = x4[2 * (lane + 32 * m)];
                    float4 xb = x4[2 * (lane + 32 * m) + 1];
                    float2 f0 = __bfloat1622float2(*reinterpret_cast<const __nv_bfloat162*>(&u.x));
                    float2 f1 = __bfloat1622float2(*reinterpret_cast<const __nv_bfloat162*>(&u.y));
                    float2 f2 = __bfloat1622float2(*reinterpret_cast<const __nv_bfloat162*>(&u.z));
                    float2 f3 = __bfloat1622float2(*reinterpret_cast<const __nv_bfloat162*>(&u.w));
                    s = fmaf(f0.x, xa.x, fmaf(f0.y, xa.y, fmaf(f1.x, xa.z, fmaf(f1.y, xa.w, s))));
                    s = fmaf(f2.x, xb.x, fmaf(f2.y, xb.y, fmaf(f3.x, xb.z, fmaf(f3.y, xb.w, s))));
                }
                s = wred(s);
                if (lane == 0) {
                    s += b_lt[r];
                    g_bfsc[r] = s;
                    unsigned long long k = packmax(s, r);
                    if (k > best) best = k;
                }
            }
            if (lane == 0) s_best[w] = best;
            __syncthreads();
            if (threadIdx.x == 0) {
                unsigned long long m = 0ull;
                for (int i = 0; i < WPB; ++i) if (s_best[i] > m) m = s_best[i];
                atomicMax(&g_bfmax, m);
            }
        }
        gbar(++gen);

        // ----- phase C2: fp32 rescore of candidates within sound margin -> exact argmax -----
        {
            // Per-element bf16 round-off <= 2^-8 |w|  =>  |bf_score - fp_score| <= 2^-8 ||W_r|| ||h||
            // (Cauchy-Schwarz) = e.  Inclusion guarantee needs margin >= 2e = 2^-7 ||W||max ||h||.
            // 4 * 0.001953125 = 2^-7 exactly, with ||W||max over-estimating all non-max rows.
            float wn = sqrtf(__uint_as_float(g_wmax_bits));
            float hn = sqrtf(g_hnorm2);
            float cut = unpackval(g_bfmax) - 4.0f * 0.001953125f * wn * hn;
            unsigned long long best = 0ull;
            for (int r = JID; r < V; r += TW) {
                if (g_bfsc[r] >= cut) {
                    float p = dp1024(W_lt + (size_t)r * H, g_htall + t * H, lane);
                    p = wred(p);
                    if (lane == 0) {
                        p += b_lt[r];
                        unsigned long long k = packmax(p, r);
                        if (k > best) best = k;
                    }
                }
            }
            if (lane == 0) s_best[w] = best;
            __syncthreads();
            if (threadIdx.x == 0) {
                unsigned long long m = 0ull;
                for (int i = 0; i < WPB; ++i) if (s_best[i] > m) m = s_best[i];
                if (m) atomicMax(&g_amax[t & 1], m);
            }
        }
        gbar(++gen);
    }

    // ---------- deferred logits: one fp32 pass over W_lt, all 51 steps ----------
    // ht_new vectors in smem; 2 rows/warp register-resident; SAME fma order as dp1024
    for (int idx = threadIdx.x; idx < NSTEPS * 256; idx += NTHR)
        s_dyn4[idx] = ((const float4*)g_htall)[idx];
    __syncthreads();
    for (int rp = JID; rp < V / 2; rp += TW) {
        int r = rp * 2;
        const float4* wa = (const float4*)(W_lt + (size_t)r * H);
        const float4* wb = (const float4*)(W_lt + (size_t)(r + 1) * H);
        float4 A[8], B[8];
#pragma unroll
        for (int k = 0; k < 8; ++k) { A[k] = __ldcs(wa + lane + 32 * k); B[k] = __ldcs(wb + lane + 32 * k); }
        float ba = b_lt[r], bb = b_lt[r + 1];
        for (int t = 0; t < NSTEPS; ++t) {
            const float4* e4 = s_dyn4 + t * 256;
            float pa = 0.f, pb = 0.f;
#pragma unroll
            for (int k = 0; k < 8; ++k) {
                float4 e = e4[lane + 32 * k];
                pa = fmaf(A[k].x, e.x, fmaf(A[k].y, e.y, fmaf(A[k].z, e.z, fmaf(A[k].w, e.w, pa))));
                pb = fmaf(B[k].x, e.x, fmaf(B[k].y, e.y, fmaf(B[k].z, e.z, fmaf(B[k].w, e.w, pb))));
            }
            pa = wred(pa);
            pb = wred(pb);
            if (lane == 0) {
                __stcs(logits_out + (size_t)t * V + r,     pa + ba);
                __stcs(logits_out + (size_t)t * V + r + 1, pb + bb);
            }
        }
    }

    // ---------- epilogue: last token ----------
    if (blockIdx.x == 0 && threadIdx.x == 0) {
        int wn = unpackidx(g_amax[(NSTEPS - 1) & 1]);
        int ot = (done || wn == EOS_ID) ? -1 : wn;
        toks_out[NSTEPS - 1] = (float)ot;
    }
}

// ---------------- host launcher ----------------
extern "C" void kernel_launch(void* const* d_in, const int* in_sizes, int n_in,
                              void* d_out, int out_size) {
    const int*   src_ids = (const int*)  d_in[0];
    const float* emb_in  = (const float*)d_in[1];
    const float* Wih_e   = (const float*)d_in[2];
    const float* Whh_e   = (const float*)d_in[3];
    const float* bih_e   = (const float*)d_in[4];
    const float* bhh_e   = (const float*)d_in[5];
    const float* W_li    = (const float*)d_in[6];
    const float* b_li    = (const float*)d_in[7];
    const float* emb_t   = (const float*)d_in[8];
    const float* Wih_d   = (const float*)d_in[9];
    const float* Whh_d   = (const float*)d_in[10];
    const float* bih_d   = (const float*)d_in[11];
    const float* bhh_d   = (const float*)d_in[12];
    const float* W_lt    = (const float*)d_in[13];
    const float* b_lt    = (const float*)d_in[14];
    const float* W_tl    = (const float*)d_in[15];
    const float* b_tl    = (const float*)d_in[16];

    float* out = (float*)d_out;
    float* scratch = nullptr;
    cudaGetSymbolAddress((void**)&scratch, g_scratch);

    float* toks_out   = scratch + (size_t)NSTEPS * V;
    float* logits_out = scratch;
    if (out_size >= NSTEPS * V + NSTEPS) {        // (toks, logits) concatenated
        toks_out   = out;
        logits_out = out + NSTEPS;
    } else if (out_size >= NSTEPS * V) {          // logits only
        logits_out = out;
    } else if (out_size >= NSTEPS) {              // toks only
        toks_out = out;
    }

    cudaFuncSetAttribute(seq2seq_kernel,
                         cudaFuncAttributeMaxDynamicSharedMemorySize, DYN_SMEM);

    init_k<<<1, 256>>>();
    seq2seq_kernel<<<NBLK, NTHR, DYN_SMEM>>>(src_ids, emb_in, Wih_e, Whh_e, bih_e, bhh_e,
                                             W_li, b_li, emb_t, Wih_d, Whh_d, bih_d, bhh_d,
                                             W_lt, b_lt, W_tl, b_tl, toks_out, logits_out);
}